// round 15
// baseline (speedup 1.0000x reference)
#include <cuda_runtime.h>
#include <cstdint>

// Tridiagonal Thomas solve with precomputed LU factors, chunked with
// exponential-decay halos (|c|,|w| <= 1/3 => 0.268^16 ~ 7e-10 warmup error).
//
// R15 = R14 (warp-autonomous 32x96 smem tiles, cp.async, .cs stores)
//  + L2 evict_last policy on x tile loads (x ~fits L2: keep it resident,
//    z stores are evict-first so they never displace it)
//  + coefficient setup fused into the solve kernel (one launch total):
//    each block derives its 96-wide cc/(1/a)/w window from a,b,c inline.

#define L_CHUNK 64
#define HALO    16
#define CW      (L_CHUNK + 2 * HALO)   // 96 columns max per tile
#define ROWS    32                     // rows per block == threads per block
#define TS      100                    // tile row stride (floats): 25 f4, odd -> conflict-free .128

__device__ __forceinline__ uint32_t smem_u32(const void* p) {
    return (uint32_t)__cvta_generic_to_shared(p);
}

__device__ __forceinline__ uint64_t mk_evict_last_policy() {
    uint64_t pol;
    asm("createpolicy.fractional.L2::evict_last.b64 %0, 1.0;" : "=l"(pol));
    return pol;
}

__device__ __forceinline__ void cp16_el(uint32_t dst, const float* src,
                                        uint64_t pol) {
    asm volatile("cp.async.cg.shared.global.L2::cache_hint [%0], [%1], 16, %2;\n"
                 :: "r"(dst), "l"(src), "l"(pol));
}

__device__ __forceinline__ void stg128_cs(float* p, float4 v) {
    asm volatile("st.global.cs.v4.f32 [%0], {%1, %2, %3, %4};\n"
                 :: "l"(p), "f"(v.x), "f"(v.y), "f"(v.z), "f"(v.w)
                 : "memory");
}

__global__ void __launch_bounds__(ROWS)
solve_kernel(const float* __restrict__ x, float* __restrict__ z,
             const float* __restrict__ ga, const float* __restrict__ gb,
             const float* __restrict__ gc, int N) {
    __shared__ float tile[ROWS * TS];              // 32*100*4 = 12.5 KB
    __shared__ float cc_s[CW], ia_s[CW], w_s[CW];  // 1.15 KB

    const int lane = threadIdx.x;                   // 0..31
    const int s    = blockIdx.x * L_CHUNK;          // chunk start
    const int c0   = max(s - HALO, 0);              // tile col range [c0, c1)
    const int c1   = min(s + L_CHUNK + HALO, N);
    const int ncol = c1 - c0;                       // 80 or 96, multiple of 16
    const int nf4  = ncol >> 2;                     // 20 or 24 float4 per row (<= 32)
    const int jlo  = s - c0;                        // 0 (first chunk) or 16
    const int r0   = blockIdx.y * ROWS;

    const uint64_t pol = mk_evict_last_policy();

    // ---- Fire-and-forget async tile loads (x kept L2-resident).
    {
        const float* xb = x + (size_t)r0 * N + c0;
        const bool on = lane < nf4;
        #pragma unroll 8
        for (int r = 0; r < ROWS; ++r) {
            if (on)
                cp16_el(smem_u32(tile + r * TS) + lane * 16,
                        xb + (size_t)r * N + lane * 4, pol);
        }
        asm volatile("cp.async.commit_group;\n" ::: "memory");
    }

    // ---- Coefficients inline (L2-broadcast scalar LDGs, once per block).
    // Overlaps the in-flight cp.async group.
    for (int j = lane; j < ncol; j += 32) {
        int col = c0 + j;
        float ia = 1.0f / ga[col];
        cc_s[j] = (col == 0) ? 0.0f : gc[col - 1];
        ia_s[j] = ia;
        w_s[j]  = (col < N - 1) ? gb[col] * ia : 0.0f;
    }

    asm volatile("cp.async.wait_group 0;\n" ::: "memory");
    __syncwarp();

    // ---- Per-thread row solve (thread == row), in place in the tile row.
    {
        float* tr = tile + lane * TS;

        // Forward: y[i] = x[i] - y[i-1]*cc[i]; store u = y/a (off-chain mul).
        float y = 0.0f;   // exact for c0==0 (cc[0]=0); halo-warmed otherwise
        #pragma unroll 4
        for (int j = 0; j < ncol; j += 4) {
            float4 xv = *(const float4*)(tr + j);
            float4 cv = *(const float4*)(cc_s + j);
            float4 iv = *(const float4*)(ia_s + j);
            float4 u;
            y = fmaf(-y, cv.x, xv.x); u.x = y * iv.x;
            y = fmaf(-y, cv.y, xv.y); u.y = y * iv.y;
            y = fmaf(-y, cv.z, xv.z); u.z = y * iv.z;
            y = fmaf(-y, cv.w, xv.w); u.w = y * iv.w;
            *(float4*)(tr + j) = u;
        }

        // Backward: z[i] = u[i] - w[i]*z[i+1]  (single-FMA 4-cycle chain).
        float zv = 0.0f;  // exact for c1==N (w[N-1]=0); halo-warmed otherwise
        #pragma unroll 4
        for (int j = ncol - 4; j >= jlo; j -= 4) {
            float4 uv = *(const float4*)(tr + j);
            float4 wv = *(const float4*)(w_s + j);
            float4 zo;
            zv = fmaf(-zv, wv.w, uv.w); zo.w = zv;
            zv = fmaf(-zv, wv.z, uv.z); zo.z = zv;
            zv = fmaf(-zv, wv.y, uv.y); zo.y = zv;
            zv = fmaf(-zv, wv.x, uv.x); zo.x = zv;
            *(float4*)(tr + j) = zo;
        }
    }
    __syncwarp();

    // ---- Store interior [jlo, jlo+64): 16 f4 per row, 2 rows per warp-iter.
    // LDS.128 conflict-free (row stride 25 f4, odd), STG.128.CS coalesced
    // (evict-first in L2 so the output stream does not evict resident x).
    {
        float* zb = z + (size_t)r0 * N + s;
        const int nout = ROWS * (L_CHUNK / 4);     // 512
        #pragma unroll 16
        for (int i = lane; i < nout; i += 32) {
            int row = i >> 4;
            int c4  = i & 15;
            float4 v = *(const float4*)(tile + row * TS + jlo + c4 * 4);
            stg128_cs(zb + (size_t)row * N + c4 * 4, v);
        }
    }
}

extern "C" void kernel_launch(void* const* d_in, const int* in_sizes, int n_in,
                              void* d_out, int out_size) {
    const float* x = (const float*)d_in[0];
    const float* a = (const float*)d_in[1];
    const float* b = (const float*)d_in[2];
    const float* c = (const float*)d_in[3];
    float* z = (float*)d_out;

    const int N = in_sizes[1];          // 8192
    const int B = in_sizes[0] / N;      // 4096

    dim3 grid(N / L_CHUNK, B / ROWS);   // 128 x 128 = 16384 blocks
    solve_kernel<<<grid, ROWS>>>(x, z, a, b, c, N);
}

// round 16
// speedup vs baseline: 1.3335x; 1.3335x over previous
#include <cuda_runtime.h>
#include <cstdint>

// Tridiagonal Thomas solve with precomputed LU factors, chunked with
// exponential-decay halos (|c|,|w| <= 1/3 => 0.268^16 ~ 7e-10 warmup error).
//
// R16 = R9 (best kernel config: one block == one warp, 32 rows x
// (128 + 2*16) cols, ~23 KB smem -> 9 independent pipelines/SM, all loads
// one fire-and-forget cp.async group) + R14's streaming stores
// (st.global.cs: z is write-once, evict-first keeps it from thrashing
// L2-resident x).

#define L_CHUNK 128
#define HALO    16
#define CW      (L_CHUNK + 2 * HALO)   // 160 columns max per tile
#define ROWS    32                     // rows per block == threads per block
#define TS      164                    // tile row stride (floats): 41 f4, odd -> conflict-free .128
#define MAXN    8192

__device__ float g_cc[MAXN];   // cc[i] = c[i-1], cc[0] = 0
__device__ float g_ia[MAXN];   // 1 / a[i]
__device__ float g_w [MAXN];   // b[i] / a[i], w[N-1] = 0

__global__ void setup_coeffs(const float* __restrict__ a,
                             const float* __restrict__ b,
                             const float* __restrict__ c, int N) {
    int i = blockIdx.x * blockDim.x + threadIdx.x;
    if (i < N) {
        g_cc[i] = (i == 0) ? 0.0f : c[i - 1];
        float ia = 1.0f / a[i];
        g_ia[i] = ia;
        g_w[i]  = (i < N - 1) ? b[i] * ia : 0.0f;
    }
}

__device__ __forceinline__ uint32_t smem_u32(const void* p) {
    return (uint32_t)__cvta_generic_to_shared(p);
}

__device__ __forceinline__ void cp16(uint32_t dst, const float* src) {
    asm volatile("cp.async.cg.shared.global [%0], [%1], 16;\n"
                 :: "r"(dst), "l"(src));
}

__device__ __forceinline__ void stg128_cs(float* p, float4 v) {
    asm volatile("st.global.cs.v4.f32 [%0], {%1, %2, %3, %4};\n"
                 :: "l"(p), "f"(v.x), "f"(v.y), "f"(v.z), "f"(v.w)
                 : "memory");
}

__global__ void __launch_bounds__(ROWS)
solve_kernel(const float* __restrict__ x, float* __restrict__ z, int N) {
    __shared__ float tile[ROWS * TS];              // 32*164*4 = 21.0 KB
    __shared__ float cc_s[CW], ia_s[CW], w_s[CW];  // 1.92 KB

    const int lane = threadIdx.x;                   // 0..31
    const int s    = blockIdx.x * L_CHUNK;          // chunk start
    const int c0   = max(s - HALO, 0);              // tile col range [c0, c1)
    const int c1   = min(s + L_CHUNK + HALO, N);
    const int ncol = c1 - c0;                       // 144 or 160, multiple of 16
    const int nf4  = ncol >> 2;                     // 36 or 40 float4 per row
    const int jlo  = s - c0;                        // 0 (first chunk) or 16
    const int r0   = blockIdx.y * ROWS;

    // ---- Fire-and-forget async loads: whole tile + coefficients, one group.
    {
        const float* xb = x + (size_t)r0 * N + c0;
        #pragma unroll 8
        for (int r = 0; r < ROWS; ++r) {
            const float* xr = xb + (size_t)r * N;
            uint32_t dst = smem_u32(tile + r * TS);
            cp16(dst + lane * 16, xr + lane * 4);          // lanes 0..31 < nf4
            if (lane + 32 < nf4)
                cp16(dst + (lane + 32) * 16, xr + (lane + 32) * 4);
        }
        // Coefficients (c0 is a multiple of 16 floats -> 16B-aligned f4 src).
        {
            uint32_t d_cc = smem_u32(cc_s), d_ia = smem_u32(ia_s), d_w = smem_u32(w_s);
            cp16(d_cc + lane * 16, g_cc + c0 + lane * 4);
            cp16(d_ia + lane * 16, g_ia + c0 + lane * 4);
            cp16(d_w  + lane * 16, g_w  + c0 + lane * 4);
            if (lane + 32 < nf4) {
                cp16(d_cc + (lane + 32) * 16, g_cc + c0 + (lane + 32) * 4);
                cp16(d_ia + (lane + 32) * 16, g_ia + c0 + (lane + 32) * 4);
                cp16(d_w  + (lane + 32) * 16, g_w  + c0 + (lane + 32) * 4);
            }
        }
        asm volatile("cp.async.commit_group;\n" ::: "memory");
        asm volatile("cp.async.wait_group 0;\n" ::: "memory");
    }
    __syncwarp();

    // ---- Per-thread row solve (thread == row), fully in place in tile row.
    {
        float* tr = tile + lane * TS;

        // Forward: y[i] = x[i] - y[i-1]*cc[i]; store u = y/a (off-chain mul).
        float y = 0.0f;   // exact for c0==0 (cc[0]=0); halo-warmed otherwise
        #pragma unroll 4
        for (int j = 0; j < ncol; j += 4) {
            float4 xv = *(const float4*)(tr + j);
            float4 cv = *(const float4*)(cc_s + j);
            float4 iv = *(const float4*)(ia_s + j);
            float4 u;
            y = fmaf(-y, cv.x, xv.x); u.x = y * iv.x;
            y = fmaf(-y, cv.y, xv.y); u.y = y * iv.y;
            y = fmaf(-y, cv.z, xv.z); u.z = y * iv.z;
            y = fmaf(-y, cv.w, xv.w); u.w = y * iv.w;
            *(float4*)(tr + j) = u;
        }

        // Backward: z[i] = u[i] - w[i]*z[i+1]  (single-FMA 4-cycle chain).
        float zv = 0.0f;  // exact for c1==N (w[N-1]=0); halo-warmed otherwise
        #pragma unroll 4
        for (int j = ncol - 4; j >= jlo; j -= 4) {
            float4 uv = *(const float4*)(tr + j);
            float4 wv = *(const float4*)(w_s + j);
            float4 zo;
            zv = fmaf(-zv, wv.w, uv.w); zo.w = zv;
            zv = fmaf(-zv, wv.z, uv.z); zo.z = zv;
            zv = fmaf(-zv, wv.y, uv.y); zo.y = zv;
            zv = fmaf(-zv, wv.x, uv.x); zo.x = zv;
            *(float4*)(tr + j) = zo;
        }
    }
    __syncwarp();

    // ---- Store interior [jlo, jlo+128): lane == f4 column, one row/iter.
    // LDS.128 consecutive within a row (conflict-free), STG.128.CS coalesced
    // (evict-first: the write-once output stream must not displace x in L2).
    {
        float* zb = z + (size_t)r0 * N + s;
        const float* tb = tile + jlo;
        #pragma unroll 8
        for (int r = 0; r < ROWS; ++r) {
            float4 v = *(const float4*)(tb + r * TS + lane * 4);
            stg128_cs(zb + (size_t)r * N + lane * 4, v);
        }
    }
}

extern "C" void kernel_launch(void* const* d_in, const int* in_sizes, int n_in,
                              void* d_out, int out_size) {
    const float* x = (const float*)d_in[0];
    const float* a = (const float*)d_in[1];
    const float* b = (const float*)d_in[2];
    const float* c = (const float*)d_in[3];
    float* z = (float*)d_out;

    const int N = in_sizes[1];          // 8192
    const int B = in_sizes[0] / N;      // 4096

    setup_coeffs<<<(N + 255) / 256, 256>>>(a, b, c, N);

    dim3 grid(N / L_CHUNK, B / ROWS);   // 64 x 128 = 8192 blocks
    solve_kernel<<<grid, ROWS>>>(x, z, N);
}